// round 5
// baseline (speedup 1.0000x reference)
#include <cuda_runtime.h>
#include <cstdint>
#include <math.h>

// x [128, 1, 512, 512] fp32.
//   pred = softplus(x); m = max over sample; out = (m > 1e-8) ? pred/m : pred.
// softplus monotone => m = softplus(max(x)).
//
// R5 (= R4 + missing <cstdint>): single fused kernel using 8-CTA clusters
// (one cluster per sample). Each CTA stages its 128 KB chunk in dynamic SMEM
// while reducing the chunk max, exchanges partial maxes via DSMEM +
// cluster.sync, then re-reads its chunk from SMEM (each thread re-reads its
// own values) for softplus*scale. DRAM traffic = one streaming read + one
// streaming write (268 MB total); input never re-read from L2/DRAM. One node.

#define SAMPLES 128
#define SAMPLE_ELEMS (512 * 512)          // 262144 floats per sample
#define CLUSTER 8                         // CTAs per sample
#define THREADS 1024
#define CTA_N4 (SAMPLE_ELEMS / CLUSTER / 4)   // 8192 float4 per CTA (128 KB)
#define ITERS (CTA_N4 / THREADS)              // 8 float4 per thread
#define SMEM_BYTES (CTA_N4 * 16)              // 131072
#define EPS 1e-8f

__device__ __forceinline__ float softplus_f(float x) {
    // Stable: max(x,0) + log1p(exp(-|x|)), matches jnp.logaddexp(x, 0).
    return fmaxf(x, 0.0f) + log1pf(__expf(-fabsf(x)));
}

__device__ __forceinline__ unsigned int smem_u32(const void* p) {
    unsigned int a;
    asm("{ .reg .u64 t; cvta.to.shared.u64 t, %1; cvt.u32.u64 %0, t; }"
        : "=r"(a) : "l"(p));
    return a;
}

__global__ __launch_bounds__(THREADS, 1) __cluster_dims__(CLUSTER, 1, 1)
void fused_norm_kernel(const float* __restrict__ x, float* __restrict__ out) {
    extern __shared__ float4 stage[];            // 8192 float4 = 128 KB
    __shared__ float s_cta_max;                  // this CTA's partial max
    __shared__ float s_scale;
    __shared__ float s_red[THREADS / 32];

    const int tid = threadIdx.x;

    // Global chunk: cluster c covers sample c; rank r covers chunk r.
    const size_t base4 = (size_t)blockIdx.x * CTA_N4;   // blockIdx.x = c*8 + r
    const float4* __restrict__ xin = reinterpret_cast<const float4*>(x) + base4;
    float4* __restrict__ o = reinterpret_cast<float4*>(out) + base4;

    // ---------- Phase 1: stream chunk into SMEM, reduce chunk max ----------
    float m0 = -INFINITY, m1 = -INFINITY;
    #pragma unroll
    for (int i = 0; i < ITERS; i += 2) {
        float4 a = __ldcs(&xin[i * THREADS + tid]);
        float4 b = __ldcs(&xin[(i + 1) * THREADS + tid]);
        stage[i * THREADS + tid] = a;
        stage[(i + 1) * THREADS + tid] = b;
        m0 = fmaxf(m0, fmaxf(fmaxf(a.x, a.y), fmaxf(a.z, a.w)));
        m1 = fmaxf(m1, fmaxf(fmaxf(b.x, b.y), fmaxf(b.z, b.w)));
    }
    float m = fmaxf(m0, m1);

    #pragma unroll
    for (int off = 16; off; off >>= 1)
        m = fmaxf(m, __shfl_xor_sync(0xFFFFFFFFu, m, off));
    if ((tid & 31) == 0) s_red[tid >> 5] = m;
    __syncthreads();
    if (tid < (THREADS / 32)) {
        float v = s_red[tid];
        #pragma unroll
        for (int off = (THREADS / 64); off; off >>= 1)
            v = fmaxf(v, __shfl_xor_sync(0xFFFFFFFFu, v, off));
        if (tid == 0) s_cta_max = v;
    }
    __syncthreads();

    // ---------- Cluster exchange of 8 partial maxes ----------
    // arrive has release semantics for the s_cta_max store; wait has acquire.
    asm volatile("barrier.cluster.arrive.aligned;" ::: "memory");
    asm volatile("barrier.cluster.wait.aligned;" ::: "memory");

    if (tid == 0) {
        const unsigned int local = smem_u32(&s_cta_max);
        float allm = -INFINITY;
        #pragma unroll
        for (int r = 0; r < CLUSTER; r++) {
            unsigned int remote;
            float v;
            asm("mapa.shared::cluster.u32 %0, %1, %2;"
                : "=r"(remote) : "r"(local), "r"(r));
            asm("ld.shared::cluster.f32 %0, [%1];" : "=f"(v) : "r"(remote));
            allm = fmaxf(allm, v);
        }
        float sm = softplus_f(allm);        // = max(softplus(x)) by monotonicity
        s_scale = (sm > EPS) ? (1.0f / sm) : 1.0f;
    }
    __syncthreads();
    const float scale = s_scale;

    // ---------- Phase 2: softplus * scale from SMEM, streaming store ----------
    #pragma unroll
    for (int i = 0; i < ITERS; i++) {
        float4 v = stage[i * THREADS + tid];
        float4 r;
        r.x = softplus_f(v.x) * scale;
        r.y = softplus_f(v.y) * scale;
        r.z = softplus_f(v.z) * scale;
        r.w = softplus_f(v.w) * scale;
        __stcs(&o[i * THREADS + tid], r);
    }

    // No CTA may exit while peers might still read its DSMEM.
    asm volatile("barrier.cluster.arrive.aligned;" ::: "memory");
    asm volatile("barrier.cluster.wait.aligned;" ::: "memory");
}

extern "C" void kernel_launch(void* const* d_in, const int* in_sizes, int n_in,
                              void* d_out, int out_size) {
    const float* x = (const float*)d_in[0];
    float* out = (float*)d_out;
    static bool attr_set = false;
    if (!attr_set) {
        cudaFuncSetAttribute(fused_norm_kernel,
                             cudaFuncAttributeMaxDynamicSharedMemorySize,
                             SMEM_BYTES);
        attr_set = true;
    }
    int samples = in_sizes[0] / SAMPLE_ELEMS;     // 128
    fused_norm_kernel<<<samples * CLUSTER, THREADS, SMEM_BYTES>>>(x, out);
}

// round 6
// speedup vs baseline: 1.4996x; 1.4996x over previous
#include <cuda_runtime.h>
#include <cstdint>
#include <math.h>

// x [128, 1, 512, 512] fp32.
//   pred = softplus(x); m = max over sample; out = (m > 1e-8) ? pred/m : pred.
// softplus monotone => m = softplus(max(x)).
//
// R6: two-kernel graph (R3 minus its measured overheads).
//   K1: per-CTA max of a 2048-float4 chunk -> plain store to a DISTINCT slot
//       g_partial[blockIdx.x]. No atomics, no reset kernel (saves the 4.26us
//       reset node R3 profiled + one launch). Default loads keep input in L2.
//   K2: one warp reduces the sample's 32 partials, then streaming
//       softplus*scale: __ldcs loads (last use, mostly L2 hits), __stcs stores
//       (don't evict input lines other CTAs still need).

#define SAMPLES 128
#define SAMPLE_ELEMS (512 * 512)        // 262144
#define SAMPLE_N4 (SAMPLE_ELEMS / 4)    // 65536 float4
#define CHUNKS 32                       // CTAs per sample
#define CHUNK_N4 (SAMPLE_N4 / CHUNKS)   // 2048 float4 per CTA
#define THREADS 256                     // 8 float4 per thread
#define EPS 1e-8f

__device__ float g_partial[SAMPLES * CHUNKS];   // written every call before read

__device__ __forceinline__ float softplus_f(float x) {
    // Stable: max(x,0) + log1p(exp(-|x|)), matches jnp.logaddexp(x, 0).
    return fmaxf(x, 0.0f) + log1pf(__expf(-fabsf(x)));
}

// ---------- K1: per-chunk max ----------
__global__ __launch_bounds__(THREADS)
void max_kernel(const float* __restrict__ x) {
    const float4* __restrict__ xin =
        reinterpret_cast<const float4*>(x) + (size_t)blockIdx.x * CHUNK_N4;
    const int tid = threadIdx.x;

    // 8 float4 per thread, 4 independent accumulators (short FMNMX chains).
    float m0 = -INFINITY, m1 = -INFINITY, m2 = -INFINITY, m3 = -INFINITY;
    #pragma unroll
    for (int it = 0; it < 2; it++) {
        int base = it * 4 * THREADS + tid;
        float4 a = xin[base];
        float4 b = xin[base + THREADS];
        float4 c = xin[base + 2 * THREADS];
        float4 d = xin[base + 3 * THREADS];
        m0 = fmaxf(m0, fmaxf(fmaxf(a.x, a.y), fmaxf(a.z, a.w)));
        m1 = fmaxf(m1, fmaxf(fmaxf(b.x, b.y), fmaxf(b.z, b.w)));
        m2 = fmaxf(m2, fmaxf(fmaxf(c.x, c.y), fmaxf(c.z, c.w)));
        m3 = fmaxf(m3, fmaxf(fmaxf(d.x, d.y), fmaxf(d.z, d.w)));
    }
    float m = fmaxf(fmaxf(m0, m1), fmaxf(m2, m3));

    #pragma unroll
    for (int off = 16; off; off >>= 1)
        m = fmaxf(m, __shfl_xor_sync(0xFFFFFFFFu, m, off));

    __shared__ float red[THREADS / 32];
    if ((tid & 31) == 0) red[tid >> 5] = m;
    __syncthreads();
    if (tid < (THREADS / 32)) {
        float v = red[tid];
        #pragma unroll
        for (int off = (THREADS / 64); off; off >>= 1)
            v = fmaxf(v, __shfl_xor_sync(0xFFFFFFFFu, v, off));
        if (tid == 0) g_partial[blockIdx.x] = v;    // distinct slot, no atomic
    }
}

// ---------- K2: reduce partials + normalize ----------
__global__ __launch_bounds__(THREADS)
void norm_kernel(const float* __restrict__ x, float* __restrict__ out) {
    const int sample = blockIdx.x >> 5;             // / CHUNKS
    const size_t off4 = (size_t)blockIdx.x * CHUNK_N4;
    const float4* __restrict__ xin = reinterpret_cast<const float4*>(x) + off4;
    float4* __restrict__ o = reinterpret_cast<float4*>(out) + off4;
    const int tid = threadIdx.x;

    __shared__ float s_scale;
    if (tid < 32) {
        float v = g_partial[sample * CHUNKS + tid]; // CHUNKS == 32
        #pragma unroll
        for (int off = 16; off; off >>= 1)
            v = fmaxf(v, __shfl_xor_sync(0xFFFFFFFFu, v, off));
        if (tid == 0) {
            float sm = softplus_f(v);   // = max(softplus(x)) by monotonicity
            s_scale = (sm > EPS) ? (1.0f / sm) : 1.0f;
        }
    }
    __syncthreads();
    const float scale = s_scale;

    #pragma unroll
    for (int it = 0; it < 2; it++) {
        int base = it * 4 * THREADS + tid;
        float4 a = __ldcs(&xin[base]);
        float4 b = __ldcs(&xin[base + THREADS]);
        float4 c = __ldcs(&xin[base + 2 * THREADS]);
        float4 d = __ldcs(&xin[base + 3 * THREADS]);
        float4 ra, rb, rc, rd;
        ra.x = softplus_f(a.x) * scale; ra.y = softplus_f(a.y) * scale;
        ra.z = softplus_f(a.z) * scale; ra.w = softplus_f(a.w) * scale;
        rb.x = softplus_f(b.x) * scale; rb.y = softplus_f(b.y) * scale;
        rb.z = softplus_f(b.z) * scale; rb.w = softplus_f(b.w) * scale;
        rc.x = softplus_f(c.x) * scale; rc.y = softplus_f(c.y) * scale;
        rc.z = softplus_f(c.z) * scale; rc.w = softplus_f(c.w) * scale;
        rd.x = softplus_f(d.x) * scale; rd.y = softplus_f(d.y) * scale;
        rd.z = softplus_f(d.z) * scale; rd.w = softplus_f(d.w) * scale;
        __stcs(&o[base], ra);
        __stcs(&o[base + THREADS], rb);
        __stcs(&o[base + 2 * THREADS], rc);
        __stcs(&o[base + 3 * THREADS], rd);
    }
}

extern "C" void kernel_launch(void* const* d_in, const int* in_sizes, int n_in,
                              void* d_out, int out_size) {
    const float* x = (const float*)d_in[0];
    float* out = (float*)d_out;
    int samples = in_sizes[0] / SAMPLE_ELEMS;       // 128
    max_kernel<<<samples * CHUNKS, THREADS>>>(x);
    norm_kernel<<<samples * CHUNKS, THREADS>>>(x, out);
}

// round 7
// speedup vs baseline: 1.7411x; 1.1611x over previous
#include <cuda_runtime.h>
#include <cstdint>
#include <math.h>

// x [128, 1, 512, 512] fp32.
//   pred = softplus(x); m = max over sample; out = (m > 1e-8) ? pred/m : pred.
// softplus monotone => m = softplus(max(x)).
//
// R7 = R6 structure + cheap softplus in the hot kernel.
// R6 profile: K2 was issue/ALU-bound (alu 51%, issue 76%) from log1pf's
// software polynomial. Replace with MUFU form:
//   softplus(x) = relu(x) + ln2 * lg2(1 + ex2(-log2e * |x|))
// = 5 alu/fma + 2 MUFU per element (vs ~20). |x| <= ~5.5 for this data, so
// t = e^-|x| >= 4e-3 and the fast-log absolute error (~2^-21) is harmless.
// The single per-sample scale still uses the accurate log1pf path.

#define SAMPLES 128
#define SAMPLE_ELEMS (512 * 512)        // 262144
#define SAMPLE_N4 (SAMPLE_ELEMS / 4)    // 65536 float4
#define CHUNKS 32                       // CTAs per sample
#define CHUNK_N4 (SAMPLE_N4 / CHUNKS)   // 2048 float4 per CTA
#define THREADS 256                     // 8 float4 per thread
#define EPS 1e-8f
#define LOG2E 1.4426950408889634f
#define LN2   0.6931471805599453f

__device__ float g_partial[SAMPLES * CHUNKS];   // written every call before read

__device__ __forceinline__ float softplus_accurate(float x) {
    return fmaxf(x, 0.0f) + log1pf(__expf(-fabsf(x)));
}

__device__ __forceinline__ float ex2f(float x) {
    float r; asm("ex2.approx.ftz.f32 %0, %1;" : "=f"(r) : "f"(x)); return r;
}
__device__ __forceinline__ float lg2f(float x) {
    float r; asm("lg2.approx.ftz.f32 %0, %1;" : "=f"(r) : "f"(x)); return r;
}

// out = softplus(x) * scale, fast path.
__device__ __forceinline__ float softplus_scaled(float x, float scale, float scale_ln2) {
    float t = ex2f(-LOG2E * fabsf(x));          // e^(-|x|)
    float l = lg2f(1.0f + t);                   // log2(1 + e^-|x|)
    return fmaf(scale, fmaxf(x, 0.0f), scale_ln2 * l);
}

// ---------- K1: per-chunk max ----------
__global__ __launch_bounds__(THREADS)
void max_kernel(const float* __restrict__ x) {
    const float4* __restrict__ xin =
        reinterpret_cast<const float4*>(x) + (size_t)blockIdx.x * CHUNK_N4;
    const int tid = threadIdx.x;

    float m0 = -INFINITY, m1 = -INFINITY, m2 = -INFINITY, m3 = -INFINITY;
    #pragma unroll
    for (int it = 0; it < 2; it++) {
        int base = it * 4 * THREADS + tid;
        float4 a = xin[base];
        float4 b = xin[base + THREADS];
        float4 c = xin[base + 2 * THREADS];
        float4 d = xin[base + 3 * THREADS];
        m0 = fmaxf(m0, fmaxf(fmaxf(a.x, a.y), fmaxf(a.z, a.w)));
        m1 = fmaxf(m1, fmaxf(fmaxf(b.x, b.y), fmaxf(b.z, b.w)));
        m2 = fmaxf(m2, fmaxf(fmaxf(c.x, c.y), fmaxf(c.z, c.w)));
        m3 = fmaxf(m3, fmaxf(fmaxf(d.x, d.y), fmaxf(d.z, d.w)));
    }
    float m = fmaxf(fmaxf(m0, m1), fmaxf(m2, m3));

    #pragma unroll
    for (int off = 16; off; off >>= 1)
        m = fmaxf(m, __shfl_xor_sync(0xFFFFFFFFu, m, off));

    __shared__ float red[THREADS / 32];
    if ((tid & 31) == 0) red[tid >> 5] = m;
    __syncthreads();
    if (tid < (THREADS / 32)) {
        float v = red[tid];
        #pragma unroll
        for (int off = (THREADS / 64); off; off >>= 1)
            v = fmaxf(v, __shfl_xor_sync(0xFFFFFFFFu, v, off));
        if (tid == 0) g_partial[blockIdx.x] = v;    // distinct slot, no atomic
    }
}

// ---------- K2: reduce partials + normalize ----------
__global__ __launch_bounds__(THREADS)
void norm_kernel(const float* __restrict__ x, float* __restrict__ out) {
    const int sample = blockIdx.x >> 5;             // / CHUNKS
    const size_t off4 = (size_t)blockIdx.x * CHUNK_N4;
    const float4* __restrict__ xin = reinterpret_cast<const float4*>(x) + off4;
    float4* __restrict__ o = reinterpret_cast<float4*>(out) + off4;
    const int tid = threadIdx.x;

    __shared__ float s_scale;
    if (tid < 32) {
        float v = g_partial[sample * CHUNKS + tid]; // CHUNKS == 32
        #pragma unroll
        for (int off = 16; off; off >>= 1)
            v = fmaxf(v, __shfl_xor_sync(0xFFFFFFFFu, v, off));
        if (tid == 0) {
            float sm = softplus_accurate(v);  // = max(softplus(x)), monotone
            s_scale = (sm > EPS) ? (1.0f / sm) : 1.0f;
        }
    }
    __syncthreads();
    const float scale = s_scale;
    const float scale_ln2 = scale * LN2;

    #pragma unroll
    for (int it = 0; it < 2; it++) {
        int base = it * 4 * THREADS + tid;
        float4 a = __ldcs(&xin[base]);
        float4 b = __ldcs(&xin[base + THREADS]);
        float4 c = __ldcs(&xin[base + 2 * THREADS]);
        float4 d = __ldcs(&xin[base + 3 * THREADS]);
        float4 ra, rb, rc, rd;
        ra.x = softplus_scaled(a.x, scale, scale_ln2);
        ra.y = softplus_scaled(a.y, scale, scale_ln2);
        ra.z = softplus_scaled(a.z, scale, scale_ln2);
        ra.w = softplus_scaled(a.w, scale, scale_ln2);
        rb.x = softplus_scaled(b.x, scale, scale_ln2);
        rb.y = softplus_scaled(b.y, scale, scale_ln2);
        rb.z = softplus_scaled(b.z, scale, scale_ln2);
        rb.w = softplus_scaled(b.w, scale, scale_ln2);
        rc.x = softplus_scaled(c.x, scale, scale_ln2);
        rc.y = softplus_scaled(c.y, scale, scale_ln2);
        rc.z = softplus_scaled(c.z, scale, scale_ln2);
        rc.w = softplus_scaled(c.w, scale, scale_ln2);
        rd.x = softplus_scaled(d.x, scale, scale_ln2);
        rd.y = softplus_scaled(d.y, scale, scale_ln2);
        rd.z = softplus_scaled(d.z, scale, scale_ln2);
        rd.w = softplus_scaled(d.w, scale, scale_ln2);
        __stcs(&o[base], ra);
        __stcs(&o[base + THREADS], rb);
        __stcs(&o[base + 2 * THREADS], rc);
        __stcs(&o[base + 3 * THREADS], rd);
    }
}

extern "C" void kernel_launch(void* const* d_in, const int* in_sizes, int n_in,
                              void* d_out, int out_size) {
    const float* x = (const float*)d_in[0];
    float* out = (float*)d_out;
    int samples = in_sizes[0] / SAMPLE_ELEMS;       // 128
    max_kernel<<<samples * CHUNKS, THREADS>>>(x);
    norm_kernel<<<samples * CHUNKS, THREADS>>>(x, out);
}

// round 8
// speedup vs baseline: 1.8794x; 1.0794x over previous
#include <cuda_runtime.h>
#include <cstdint>
#include <math.h>

// x [128, 1, 512, 512] fp32.
//   pred = softplus(x); m = max over sample; out = (m > 1e-8) ? pred/m : pred.
// softplus monotone => m = softplus(max(x)).
//
// R8 = R7 + batch slicing for L2 residency.
// R7 measured: K2 moved 213 MB DRAM (134 write + 79 MB re-read MISSES) because
// the 134 MB input exceeds the 126 MB L2. Process 64 samples (67 MB) per
// slice: K1a -> K2a -> K1b -> K2b. Each slice's input is fully L2-resident
// when its K2 runs, so K2 reads hit L2 and DRAM traffic drops to the
// 268 MB floor. Fast MUFU softplus (R7) kept in the hot kernel.

#define SAMPLES 128
#define SLICES 2
#define SAMPLES_PER_SLICE (SAMPLES / SLICES)     // 64
#define SAMPLE_ELEMS (512 * 512)                 // 262144
#define SAMPLE_N4 (SAMPLE_ELEMS / 4)             // 65536 float4
#define CHUNKS 32                                // CTAs per sample
#define CHUNK_N4 (SAMPLE_N4 / CHUNKS)            // 2048 float4 per CTA
#define SLICE_BLOCKS (SAMPLES_PER_SLICE * CHUNKS)  // 2048
#define THREADS 256                              // 8 float4 per thread
#define EPS 1e-8f
#define LOG2E 1.4426950408889634f
#define LN2   0.6931471805599453f

__device__ float g_partial[SAMPLES * CHUNKS];    // written every call before read

__device__ __forceinline__ float softplus_accurate(float x) {
    return fmaxf(x, 0.0f) + log1pf(__expf(-fabsf(x)));
}

__device__ __forceinline__ float ex2f(float x) {
    float r; asm("ex2.approx.ftz.f32 %0, %1;" : "=f"(r) : "f"(x)); return r;
}
__device__ __forceinline__ float lg2f(float x) {
    float r; asm("lg2.approx.ftz.f32 %0, %1;" : "=f"(r) : "f"(x)); return r;
}

// out = softplus(x) * scale, fast MUFU path (2 MUFU + ~5 alu/fma).
__device__ __forceinline__ float softplus_scaled(float x, float scale, float scale_ln2) {
    float t = ex2f(-LOG2E * fabsf(x));           // e^(-|x|)
    float l = lg2f(1.0f + t);                    // log2(1 + e^-|x|)
    return fmaf(scale, fmaxf(x, 0.0f), scale_ln2 * l);
}

// ---------- K1: per-chunk max over one slice ----------
// x_slice points at the slice start; partial_slice at its 2048 slots.
__global__ __launch_bounds__(THREADS)
void max_kernel(const float* __restrict__ x_slice, float* __restrict__ partial_slice) {
    const float4* __restrict__ xin =
        reinterpret_cast<const float4*>(x_slice) + (size_t)blockIdx.x * CHUNK_N4;
    const int tid = threadIdx.x;

    float m0 = -INFINITY, m1 = -INFINITY, m2 = -INFINITY, m3 = -INFINITY;
    #pragma unroll
    for (int it = 0; it < 2; it++) {
        int base = it * 4 * THREADS + tid;
        float4 a = xin[base];
        float4 b = xin[base + THREADS];
        float4 c = xin[base + 2 * THREADS];
        float4 d = xin[base + 3 * THREADS];
        m0 = fmaxf(m0, fmaxf(fmaxf(a.x, a.y), fmaxf(a.z, a.w)));
        m1 = fmaxf(m1, fmaxf(fmaxf(b.x, b.y), fmaxf(b.z, b.w)));
        m2 = fmaxf(m2, fmaxf(fmaxf(c.x, c.y), fmaxf(c.z, c.w)));
        m3 = fmaxf(m3, fmaxf(fmaxf(d.x, d.y), fmaxf(d.z, d.w)));
    }
    float m = fmaxf(fmaxf(m0, m1), fmaxf(m2, m3));

    #pragma unroll
    for (int off = 16; off; off >>= 1)
        m = fmaxf(m, __shfl_xor_sync(0xFFFFFFFFu, m, off));

    __shared__ float red[THREADS / 32];
    if ((tid & 31) == 0) red[tid >> 5] = m;
    __syncthreads();
    if (tid < (THREADS / 32)) {
        float v = red[tid];
        #pragma unroll
        for (int off = (THREADS / 64); off; off >>= 1)
            v = fmaxf(v, __shfl_xor_sync(0xFFFFFFFFu, v, off));
        if (tid == 0) partial_slice[blockIdx.x] = v;   // distinct slot, no atomic
    }
}

// ---------- K2: reduce partials + normalize one slice ----------
__global__ __launch_bounds__(THREADS)
void norm_kernel(const float* __restrict__ x_slice, float* __restrict__ out_slice,
                 const float* __restrict__ partial_slice) {
    const int sample = blockIdx.x >> 5;              // / CHUNKS (within slice)
    const size_t off4 = (size_t)blockIdx.x * CHUNK_N4;
    const float4* __restrict__ xin = reinterpret_cast<const float4*>(x_slice) + off4;
    float4* __restrict__ o = reinterpret_cast<float4*>(out_slice) + off4;
    const int tid = threadIdx.x;

    __shared__ float s_scale;
    if (tid < 32) {
        float v = partial_slice[sample * CHUNKS + tid];  // CHUNKS == 32
        #pragma unroll
        for (int off = 16; off; off >>= 1)
            v = fmaxf(v, __shfl_xor_sync(0xFFFFFFFFu, v, off));
        if (tid == 0) {
            float sm = softplus_accurate(v);   // = max(softplus(x)), monotone
            s_scale = (sm > EPS) ? (1.0f / sm) : 1.0f;
        }
    }
    __syncthreads();
    const float scale = s_scale;
    const float scale_ln2 = scale * LN2;

    #pragma unroll
    for (int it = 0; it < 2; it++) {
        int base = it * 4 * THREADS + tid;
        float4 a = __ldcs(&xin[base]);
        float4 b = __ldcs(&xin[base + THREADS]);
        float4 c = __ldcs(&xin[base + 2 * THREADS]);
        float4 d = __ldcs(&xin[base + 3 * THREADS]);
        float4 ra, rb, rc, rd;
        ra.x = softplus_scaled(a.x, scale, scale_ln2);
        ra.y = softplus_scaled(a.y, scale, scale_ln2);
        ra.z = softplus_scaled(a.z, scale, scale_ln2);
        ra.w = softplus_scaled(a.w, scale, scale_ln2);
        rb.x = softplus_scaled(b.x, scale, scale_ln2);
        rb.y = softplus_scaled(b.y, scale, scale_ln2);
        rb.z = softplus_scaled(b.z, scale, scale_ln2);
        rb.w = softplus_scaled(b.w, scale, scale_ln2);
        rc.x = softplus_scaled(c.x, scale, scale_ln2);
        rc.y = softplus_scaled(c.y, scale, scale_ln2);
        rc.z = softplus_scaled(c.z, scale, scale_ln2);
        rc.w = softplus_scaled(c.w, scale, scale_ln2);
        rd.x = softplus_scaled(d.x, scale, scale_ln2);
        rd.y = softplus_scaled(d.y, scale, scale_ln2);
        rd.z = softplus_scaled(d.z, scale, scale_ln2);
        rd.w = softplus_scaled(d.w, scale, scale_ln2);
        __stcs(&o[base], ra);
        __stcs(&o[base + THREADS], rb);
        __stcs(&o[base + 2 * THREADS], rc);
        __stcs(&o[base + 3 * THREADS], rd);
    }
}

extern "C" void kernel_launch(void* const* d_in, const int* in_sizes, int n_in,
                              void* d_out, int out_size) {
    const float* x = (const float*)d_in[0];
    float* out = (float*)d_out;

    float* g_partial_ptr = nullptr;
    cudaGetSymbolAddress((void**)&g_partial_ptr, g_partial);

    const size_t slice_elems = (size_t)SAMPLES_PER_SLICE * SAMPLE_ELEMS;
    for (int s = 0; s < SLICES; s++) {
        const float* xs = x + s * slice_elems;
        float* os = out + s * slice_elems;
        float* ps = g_partial_ptr + s * SLICE_BLOCKS;
        max_kernel<<<SLICE_BLOCKS, THREADS>>>(xs, ps);
        norm_kernel<<<SLICE_BLOCKS, THREADS>>>(xs, os, ps);
    }
}